// round 10
// baseline (speedup 1.0000x reference)
#include <cuda_runtime.h>

// AssociatorLoss: B=32, N=32
//   one[b,i,j,k,l] = sum_m a[b,i,m,l] * a[b,j,k,m]
//   two[b,i,j,k,l] = sum_m a[b,m,k,l] * a[b,i,j,m]
//   KL = sum two * log(two/one) / B
//
// R10: FFMA2 (fma.rn.f32x2) mainloop with
//  (1) padded cube layout: 36-float (9-float4) row stride, 148KB smem ->
//      k-strided rj4 loads become 1 wavefront (banks de-conflicted), v2 at
//      its 4-cyc/512B floor, zero address ALU / zero swizzle;
//  (2) pre-duplicated a[i,j,m] slab (u64 pairs, 8KB) -> broadcast LDS.128
//      feeds FFMA2 directly, no mov-dups for the "two" operand;
//  (3) lean regs (~95): acc 32 + rj4 16 + aj2 16 -> off the 128-reg spill
//      cliff that burned R0/R4/R5/R7/R9;
//  (4) division-free Cephes log poly -> 1 MUFU per KL term (was 2).

__device__ float g_partial[1024];
__device__ int   g_count = 0;

typedef unsigned long long u64;

#define FMA2(acc, a, b) \
    asm("fma.rn.f32x2 %0, %1, %2, %0;" : "+l"(acc) : "l"(a), "l"(b))

__device__ __forceinline__ u64 dup2(float x) {
    u64 r; unsigned u = __float_as_uint(x);
    asm("mov.b64 %0, {%1, %1};" : "=l"(r) : "r"(u));
    return r;
}
__device__ __forceinline__ void unpack2(u64 v, float& lo, float& hi) {
    unsigned a, b;
    asm("mov.b64 {%0, %1}, %2;" : "=r"(a), "=r"(b) : "l"(v));
    lo = __uint_as_float(a); hi = __uint_as_float(b);
}

// Division-free natural log (Cephes logf style): reduce to z in
// [sqrt(2)/2, sqrt(2)), degree-8 poly on f=z-1. ~1 ulp, NO MUFU.
__device__ __forceinline__ float cep_logf(float x) {
    int ix = __float_as_int(x);
    int t  = ix - 0x3f3504f3;
    int e  = t >> 23;
    float z = __int_as_float(ix - (t & 0xff800000));   // [0.7071, 1.4142)
    float f = z - 1.0f;
    float p =              7.0376836292e-2f;
    p = fmaf(p, f, -1.1514610310e-1f);
    p = fmaf(p, f,  1.1676998740e-1f);
    p = fmaf(p, f, -1.2420140846e-1f);
    p = fmaf(p, f,  1.4249322787e-1f);
    p = fmaf(p, f, -1.6668057665e-1f);
    p = fmaf(p, f,  2.0000714765e-1f);
    p = fmaf(p, f, -2.4999993993e-1f);
    p = fmaf(p, f,  3.3333331174e-1f);
    float f2 = f * f;
    float y = fmaf(f * f2, p, -0.5f * f2);             // f^3 P(f) - f^2/2
    return fmaf((float)e, 0.69314718056f, f + y);
}

// smem layout (bytes):
//   [0, 147456)        cube, padded: float4 idx C(x,y,c) = (x*32+y)*9 + c
//   [147456, 155648)   dup slab: u64 sdup[j*32+m] = {a[i,j,m], a[i,j,m]}
#define CUBE_F4(x, y, c)  (((x) * 32 + (y)) * 9 + (c))

__global__ __launch_bounds__(512, 1)
void assoc_kernel(const float* __restrict__ A, float* __restrict__ out) {
    extern __shared__ float4 sc4[];
    u64* sdup = reinterpret_cast<u64*>(reinterpret_cast<char*>(sc4) + 147456);

    const int i = blockIdx.x;                   // 0..31
    const int b = blockIdx.y;                   // 0..31
    const int tid = threadIdx.x;
    const float4* ab4 = reinterpret_cast<const float4*>(A + b * 32768);

    // ---- stage padded cube (coalesced reads, padded writes) ----
    #pragma unroll
    for (int it = 0; it < 16; ++it) {
        int g = it * 512 + tid;
        sc4[(g >> 3) * 9 + (g & 7)] = ab4[g];
    }
    // ---- stage pre-duplicated a[i,j,m] slab ----
    {
        const float* ai = A + b * 32768 + i * 1024;
        sdup[tid]       = dup2(ai[tid]);
        sdup[tid + 512] = dup2(ai[tid + 512]);
    }
    __syncthreads();

    const int lane = tid & 31;
    const int w    = tid >> 5;       // warp 0..15
    const int kq   = lane >> 3;      // 0..3 : k within group
    const int lq   = lane & 7;       // 0..7 : l-chunk (4 l's -> 2 pairs)
    const int jb   = (w & 7) * 4;    // 8 j-groups of 4
    const int khi  = w >> 3;         // k-half (0/1)

    float kl = 0.0f;

    #pragma unroll 1
    for (int p = 0; p < 4; ++p) {               // 4 phases, 4 k (via lanes)
        const int kk = khi * 16 + p * 4 + kq;   // this thread's k

        u64 acc1[4][2], acc2[4][2];             // b64 l-pairs
        #pragma unroll
        for (int jt = 0; jt < 4; ++jt) {
            acc1[jt][0] = 0ull; acc1[jt][1] = 0ull;
            acc2[jt][0] = 0ull; acc2[jt][1] = 0ull;
        }

        #pragma unroll
        for (int mc = 0; mc < 8; ++mc) {        // m = mc*4 + mm
            // a[jb+jt, k, m-chunk]: 4-addr, de-conflicted by padding (1 wf)
            float4 rj4[4];
            #pragma unroll
            for (int jt = 0; jt < 4; ++jt)
                rj4[jt] = sc4[CUBE_F4(jb + jt, kk, mc)];

            #pragma unroll
            for (int half = 0; half < 2; ++half) {
                // pre-dup'd a[i,j,m],a[i,j,m+1]: broadcast LDS.128
                ulonglong2 aj2[4];
                #pragma unroll
                for (int jt = 0; jt < 4; ++jt)
                    aj2[jt] = *reinterpret_cast<const ulonglong2*>(
                        &sdup[(jb + jt) * 32 + mc * 4 + half * 2]);

                #pragma unroll
                for (int mm2 = 0; mm2 < 2; ++mm2) {
                    const int mm = half * 2 + mm2;
                    const int m  = mc * 4 + mm;
                    ulonglong2 sm2 = *reinterpret_cast<const ulonglong2*>(
                        &sc4[CUBE_F4(i, m, lq)]);       // a[i,m,l..]
                    ulonglong2 v2  = *reinterpret_cast<const ulonglong2*>(
                        &sc4[CUBE_F4(m, kk, lq)]);      // a[m,k,l..]

                    #pragma unroll
                    for (int jt = 0; jt < 4; ++jt) {
                        u64 avd = mm2 ? aj2[jt].y : aj2[jt].x;
                        u64 rvd = dup2(((const float*)&rj4[jt])[mm]);
                        FMA2(acc2[jt][0], avd, v2.x);
                        FMA2(acc2[jt][1], avd, v2.y);
                        FMA2(acc1[jt][0], rvd, sm2.x);
                        FMA2(acc1[jt][1], rvd, sm2.y);
                    }
                }
            }
        }

        // ---- KL for this 4j x 4l tile: two * log(two/one) ----
        #pragma unroll
        for (int jt = 0; jt < 4; ++jt)
            #pragma unroll
            for (int h = 0; h < 2; ++h) {
                float t2a, t2b, t1a, t1b;
                unpack2(acc2[jt][h], t2a, t2b);
                unpack2(acc1[jt][h], t1a, t1b);
                kl = fmaf(t2a, cep_logf(__fdividef(t2a, t1a)), kl);
                kl = fmaf(t2b, cep_logf(__fdividef(t2b, t1b)), kl);
            }
    }

    // ---- deterministic block reduction ----
    #pragma unroll
    for (int o = 16; o > 0; o >>= 1)
        kl += __shfl_xor_sync(0xffffffffu, kl, o);

    __shared__ float sred[16];
    __shared__ bool  s_last;
    if ((tid & 31) == 0) sred[w] = kl;
    __syncthreads();

    if (tid == 0) {
        float s = 0.0f;
        #pragma unroll
        for (int x = 0; x < 16; ++x) s += sred[x];
        g_partial[b * 32 + i] = s;
        __threadfence();
        s_last = (atomicAdd(&g_count, 1) == 1023);
    }
    __syncthreads();

    // ---- last CTA: deterministic double-precision final reduce ----
    if (s_last && tid < 32) {
        __threadfence();
        double s = 0.0;
        #pragma unroll
        for (int it = 0; it < 32; ++it)
            s += (double)g_partial[it * 32 + tid];
        #pragma unroll
        for (int o = 16; o > 0; o >>= 1)
            s += __shfl_xor_sync(0xffffffffu, s, o);
        if (tid == 0) {
            out[0] = (float)(s * (1.0 / 32.0));   // / B
            g_count = 0;                          // reset for next graph replay
        }
    }
}

extern "C" void kernel_launch(void* const* d_in, const int* in_sizes, int n_in,
                              void* d_out, int out_size) {
    const float* A = (const float*)d_in[0];
    float* out = (float*)d_out;

    cudaFuncSetAttribute(assoc_kernel,
                         cudaFuncAttributeMaxDynamicSharedMemorySize, 155648);

    dim3 grid(32, 32);   // (i, b)
    assoc_kernel<<<grid, 512, 155648>>>(A, out);
}

// round 12
// speedup vs baseline: 1.6952x; 1.6952x over previous
#include <cuda_runtime.h>

// AssociatorLoss: B=32, N=32
//   one[b,i,j,k,l] = sum_m a[b,i,m,l] * a[b,j,k,m]
//   two[b,i,j,k,l] = sum_m a[b,m,k,l] * a[b,i,j,m]
//   KL = sum two * log(two/one) / B
//
// R11 (resubmitted after broker failure): lane=(jq,lq) mapping. Every load
// is exactly 1 crossbar wavefront:
//   v2/sm2: 8-addr x 4-bcast LDS.128 (128B eff);  aj/rj: lane-varying
//   scalar float2 (j lives in lanes -> no broadcast float4 prefetch arrays,
//   the proven spill trigger of R0/R4/R5/R7/R9/R10).
// Slab-padded cube (slab stride 289 f4, row stride 9 f4) de-conflicts the
// j-strided rj banks. FFMA2 mainloop: 240 LDS-wf per 512 FFMA2 per
// warp-phase -> crossbar 15.4K/SM < FFMA2 16.4K/SMSP = binding pipe.
// Live regs ~90: acc 32 (u64 l-pairs) + small transients.

__device__ float g_partial[1024];
__device__ int   g_count = 0;

typedef unsigned long long u64;

#define FMA2(acc, a, b) \
    asm("fma.rn.f32x2 %0, %1, %2, %0;" : "+l"(acc) : "l"(a), "l"(b))

__device__ __forceinline__ u64 dup2(float x) {
    u64 r; unsigned u = __float_as_uint(x);
    asm("mov.b64 %0, {%1, %1};" : "=l"(r) : "r"(u));
    return r;
}
__device__ __forceinline__ void unpack2(u64 v, float& lo, float& hi) {
    unsigned a, b;
    asm("mov.b64 {%0, %1}, %2;" : "=r"(a), "=r"(b) : "l"(v));
    lo = __uint_as_float(a); hi = __uint_as_float(b);
}

// Division-free natural log (Cephes style), ~1 ulp, no MUFU.
__device__ __forceinline__ float cep_logf(float x) {
    int ix = __float_as_int(x);
    int t  = ix - 0x3f3504f3;
    int e  = t >> 23;
    float z = __int_as_float(ix - (t & 0xff800000));   // [0.7071, 1.4142)
    float f = z - 1.0f;
    float p =              7.0376836292e-2f;
    p = fmaf(p, f, -1.1514610310e-1f);
    p = fmaf(p, f,  1.1676998740e-1f);
    p = fmaf(p, f, -1.2420140846e-1f);
    p = fmaf(p, f,  1.4249322787e-1f);
    p = fmaf(p, f, -1.6668057665e-1f);
    p = fmaf(p, f,  2.0000714765e-1f);
    p = fmaf(p, f, -2.4999993993e-1f);
    p = fmaf(p, f,  3.3333331174e-1f);
    float f2 = f * f;
    float y = fmaf(f * f2, p, -0.5f * f2);
    return fmaf((float)e, 0.69314718056f, f + y);
}

// Padded cube: float4 index CUBE_F4(x,y,c) = x*289 + y*9 + c   (c = l/4)
//   row stride 9 f4 (36 floats),  slab stride 289 f4 (odd -> rj banks ok)
#define CUBE_F4(x, y, c)  ((x) * 289 + (y) * 9 + (c))
#define SMEM_BYTES (32 * 289 * 16)   // 147,968 B

__global__ __launch_bounds__(512, 1)
void assoc_kernel(const float* __restrict__ A, float* __restrict__ out) {
    extern __shared__ float4 sc4[];
    const float* scf = reinterpret_cast<const float*>(sc4);

    const int i = blockIdx.x;                   // 0..31
    const int b = blockIdx.y;                   // 0..31
    const int tid = threadIdx.x;
    const float4* ab4 = reinterpret_cast<const float4*>(A + b * 32768);

    // ---- stage padded cube (coalesced reads, padded writes) ----
    #pragma unroll
    for (int it = 0; it < 16; ++it) {
        int g = it * 512 + tid;                 // g = x*256 + y*8 + c
        sc4[(g >> 8) * 289 + ((g >> 3) & 31) * 9 + (g & 7)] = ab4[g];
    }
    __syncthreads();

    const int lane = tid & 31;
    const int w    = tid >> 5;       // warp 0..15
    const int jq   = lane & 3;       // 4 j in lanes
    const int lq   = lane >> 2;      // 8 l-chunks (4 l each) in lanes
    const int jb   = (w & 7) * 4;    // 8 j-groups
    const int khi  = w >> 3;         // k-half
    const int j    = jb + jq;        // this thread's j

    // float-addressed bases (lane-dependent parts precomputed)
    const int aj_base = (i * 289 + j * 9) * 4;   // + m : a[i,j,m]
    const int si_base = i * 289 + lq;            // + m*9 : a[i,m,l] (f4)

    float kl = 0.0f;

    #pragma unroll 1
    for (int p = 0; p < 4; ++p) {               // phases: 4 k per phase
        const int kb = khi * 16 + p * 4;
        const int rj_base = (j * 289 + kb * 9) * 4;  // + kt*36 + m
        const int v_base  = kb * 9 + lq;             // + m*289 + kt*9 (f4)

        u64 acc1[4][2], acc2[4][2];             // [kt][l-pair]
        #pragma unroll
        for (int kt = 0; kt < 4; ++kt) {
            acc1[kt][0] = 0ull; acc1[kt][1] = 0ull;
            acc2[kt][0] = 0ull; acc2[kt][1] = 0ull;
        }

        #pragma unroll
        for (int mc = 0; mc < 16; ++mc) {       // m-pairs
            const int m0 = mc * 2;
            // lane-varying scalars (1 wf each, no broadcast arrays)
            float2 aj2 = *reinterpret_cast<const float2*>(&scf[aj_base + m0]);
            float2 rj2[4];
            #pragma unroll
            for (int kt = 0; kt < 4; ++kt)
                rj2[kt] = *reinterpret_cast<const float2*>(
                              &scf[rj_base + kt * 36 + m0]);

            #pragma unroll
            for (int h = 0; h < 2; ++h) {
                const int m = m0 + h;
                ulonglong2 sm2 = *reinterpret_cast<const ulonglong2*>(
                                     &sc4[si_base + m * 9]);    // a[i,m,l]
                u64 ajd = dup2(h ? aj2.y : aj2.x);

                #pragma unroll
                for (int kt = 0; kt < 4; ++kt) {
                    ulonglong2 v2 = *reinterpret_cast<const ulonglong2*>(
                                        &sc4[v_base + m * 289 + kt * 9]);
                    u64 rjd = dup2(h ? rj2[kt].y : rj2[kt].x);
                    FMA2(acc2[kt][0], ajd, v2.x);
                    FMA2(acc2[kt][1], ajd, v2.y);
                    FMA2(acc1[kt][0], rjd, sm2.x);
                    FMA2(acc1[kt][1], rjd, sm2.y);
                }
            }
        }

        // ---- KL for this 4k x 4l tile ----
        #pragma unroll
        for (int kt = 0; kt < 4; ++kt)
            #pragma unroll
            for (int hh = 0; hh < 2; ++hh) {
                float t2a, t2b, t1a, t1b;
                unpack2(acc2[kt][hh], t2a, t2b);
                unpack2(acc1[kt][hh], t1a, t1b);
                kl = fmaf(t2a, cep_logf(__fdividef(t2a, t1a)), kl);
                kl = fmaf(t2b, cep_logf(__fdividef(t2b, t1b)), kl);
            }
    }

    // ---- deterministic block reduction ----
    #pragma unroll
    for (int o = 16; o > 0; o >>= 1)
        kl += __shfl_xor_sync(0xffffffffu, kl, o);

    __shared__ float sred[16];
    __shared__ bool  s_last;
    if ((tid & 31) == 0) sred[w] = kl;
    __syncthreads();

    if (tid == 0) {
        float s = 0.0f;
        #pragma unroll
        for (int x = 0; x < 16; ++x) s += sred[x];
        g_partial[b * 32 + i] = s;
        __threadfence();
        s_last = (atomicAdd(&g_count, 1) == 1023);
    }
    __syncthreads();

    // ---- last CTA: deterministic double-precision final reduce ----
    if (s_last && tid < 32) {
        __threadfence();
        double s = 0.0;
        #pragma unroll
        for (int it = 0; it < 32; ++it)
            s += (double)g_partial[it * 32 + tid];
        #pragma unroll
        for (int o = 16; o > 0; o >>= 1)
            s += __shfl_xor_sync(0xffffffffu, s, o);
        if (tid == 0) {
            out[0] = (float)(s * (1.0 / 32.0));   // / B
            g_count = 0;                          // reset for next graph replay
        }
    }
}

extern "C" void kernel_launch(void* const* d_in, const int* in_sizes, int n_in,
                              void* d_out, int out_size) {
    const float* A = (const float*)d_in[0];
    float* out = (float*)d_out;

    cudaFuncSetAttribute(assoc_kernel,
                         cudaFuncAttributeMaxDynamicSharedMemorySize, SMEM_BYTES);

    dim3 grid(32, 32);   // (i, b)
    assoc_kernel<<<grid, 512, SMEM_BYTES>>>(A, out);
}

// round 13
// speedup vs baseline: 3.5477x; 2.0929x over previous
#include <cuda_runtime.h>

// AssociatorLoss: B=32, N=32
//   one[b,i,j,k,l] = sum_m a[b,i,m,l] * a[b,j,k,m]
//   two[b,i,j,k,l] = sum_m a[b,m,k,l] * a[b,i,j,m]
//   KL = sum two * log(two/one) / B
//
// R13: tensor-core reformulation. For fixed (b,i,k) both tensors are
// 32x32x32 GEMMs with IDENTICAL output fragment layouts:
//   two(j,l) = Xi(j,m) @ Y(m, k*32+l),   Xi = a[i,j,m],  Y  = a[m,k,l]
//   one(j,l) = A'(j,m) @ Wi(m,l),        A' = a[j,k,m],  Wi = a[i,m,l]
// mma.sync.m16n8k8.tf32 with 3xTF32 error compensation (Ab*Bb + Ab*Bs +
// As*Bb, residual ~2^-22 => fp32-grade accuracy). KL join happens
// register-to-register between the two C fragments. This removes the
// SIMT FFMA/LDS treadmill entirely (R6/R11: L1TEX 71-72%, issue ~26%).
// ~110 live regs, no vector prefetch arrays (the proven spill trigger).

__device__ float g_partial[1024];
__device__ int   g_count = 0;

// f32 -> tf32 (round-to-nearest-any); result is fp32 bit pattern.
__device__ __forceinline__ unsigned f2tf(float x) {
    unsigned r;
    asm("cvt.rna.tf32.f32 %0, %1;" : "=r"(r) : "f"(x));
    return r;
}

// load scf[OFF], split into big (tf32) + small (tf32 of residual)
#define LOADSPLIT(OFF, Bg, Sm) do {                       \
    float _x = scf[OFF];                                  \
    Bg = f2tf(_x);                                        \
    Sm = f2tf(_x - __uint_as_float(Bg));                  \
} while (0)

#define MMA(C, A0, A1, A2, A3, B0, B1)                                  \
    asm("mma.sync.aligned.m16n8k8.row.col.f32.tf32.tf32.f32 "           \
        "{%0,%1,%2,%3}, {%4,%5,%6,%7}, {%8,%9}, {%0,%1,%2,%3};"         \
        : "+f"(C[0]), "+f"(C[1]), "+f"(C[2]), "+f"(C[3])                \
        : "r"(A0), "r"(A1), "r"(A2), "r"(A3), "r"(B0), "r"(B1))

// Division-free natural log (Cephes style), ~1 ulp, no MUFU.
__device__ __forceinline__ float cep_logf(float x) {
    int ix = __float_as_int(x);
    int t  = ix - 0x3f3504f3;
    int e  = t >> 23;
    float z = __int_as_float(ix - (t & 0xff800000));   // [0.7071, 1.4142)
    float f = z - 1.0f;
    float p =              7.0376836292e-2f;
    p = fmaf(p, f, -1.1514610310e-1f);
    p = fmaf(p, f,  1.1676998740e-1f);
    p = fmaf(p, f, -1.2420140846e-1f);
    p = fmaf(p, f,  1.4249322787e-1f);
    p = fmaf(p, f, -1.6668057665e-1f);
    p = fmaf(p, f,  2.0000714765e-1f);
    p = fmaf(p, f, -2.4999993993e-1f);
    p = fmaf(p, f,  3.3333331174e-1f);
    float f2 = f * f;
    float y = fmaf(f * f2, p, -0.5f * f2);
    return fmaf((float)e, 0.69314718056f, f + y);
}

// SMEM (floats):
//   P1: padded natural cube, P1[x][c] at x*1032 + c, c = y*32+z (132,096 B)
//   Si: slab a[i,:,:], Si[y][z] at SI_F + y*40 + z                (5,120 B)
#define P1_STRIDE 1032
#define SI_F      33024
#define SI_F4     8256
#define SMEM_BYTES 137216

__global__ __launch_bounds__(512, 1)
void assoc_kernel(const float* __restrict__ A, float* __restrict__ out) {
    extern __shared__ float scf[];
    float4* sc4 = reinterpret_cast<float4*>(scf);

    const int i = blockIdx.x;                   // 0..31
    const int b = blockIdx.y;                   // 0..31
    const int tid = threadIdx.x;
    const float4* ab4 = reinterpret_cast<const float4*>(A + b * 32768);

    // ---- stage padded cube P1 ----
    #pragma unroll
    for (int it = 0; it < 16; ++it) {
        int gdx = it * 512 + tid;               // x*256 + c4
        sc4[(gdx >> 8) * 258 + (gdx & 255)] = ab4[gdx];
    }
    // ---- stage slab Si (stride-40 padded) ----
    if (tid < 256)
        sc4[SI_F4 + (tid >> 3) * 10 + (tid & 7)] = ab4[i * 256 + tid];
    __syncthreads();

    const int lane = tid & 31;
    const int w    = tid >> 5;       // warp 0..15
    const int g    = lane >> 2;      // groupID 0..7
    const int t    = lane & 3;       // threadID-in-group 0..3

    float kl = 0.0f;

    #pragma unroll 1
    for (int pk = 0; pk < 2; ++pk) {
        const int k = w + pk * 16;              // this warp's k

        float c1[2][4][4], c2[2][4][4];         // [mtile][ntile][4]
        #pragma unroll
        for (int mt = 0; mt < 2; ++mt)
            #pragma unroll
            for (int nt = 0; nt < 4; ++nt)
                #pragma unroll
                for (int e = 0; e < 4; ++e) { c1[mt][nt][e] = 0.f; c2[mt][nt][e] = 0.f; }

        #pragma unroll
        for (int kt = 0; kt < 4; ++kt) {        // K=32 in 4 k-tiles of 8
            const int m0 = kt * 8;
            unsigned Ab[2][4], As[2][4];

            // ===== GEMM "one":  A' = a[j,k,m] (P1),  B = Wi = Si[m][l] =====
            #pragma unroll
            for (int mt = 0; mt < 2; ++mt) {
                const int base = (mt * 16 + g) * P1_STRIDE + k * 32 + m0;
                LOADSPLIT(base + t,              Ab[mt][0], As[mt][0]);
                LOADSPLIT(base + 8 * P1_STRIDE + t,     Ab[mt][1], As[mt][1]);
                LOADSPLIT(base + t + 4,          Ab[mt][2], As[mt][2]);
                LOADSPLIT(base + 8 * P1_STRIDE + t + 4, Ab[mt][3], As[mt][3]);
            }
            #pragma unroll
            for (int nt = 0; nt < 4; ++nt) {
                unsigned Bb0, Bb1, Bs0, Bs1;
                const int boff = SI_F + (m0 + t) * 40 + nt * 8 + g;
                LOADSPLIT(boff,       Bb0, Bs0);
                LOADSPLIT(boff + 160, Bb1, Bs1);          // +4 rows * 40
                #pragma unroll
                for (int mt = 0; mt < 2; ++mt) {
                    MMA(c1[mt][nt], Ab[mt][0], Ab[mt][1], Ab[mt][2], Ab[mt][3], Bb0, Bb1);
                    MMA(c1[mt][nt], Ab[mt][0], Ab[mt][1], Ab[mt][2], Ab[mt][3], Bs0, Bs1);
                    MMA(c1[mt][nt], As[mt][0], As[mt][1], As[mt][2], As[mt][3], Bb0, Bb1);
                }
            }

            // ===== GEMM "two":  A = Xi = Si[j][m],  B = Y = a[m,k,l] (P1) =====
            #pragma unroll
            for (int mt = 0; mt < 2; ++mt) {
                const int base = SI_F + (mt * 16 + g) * 40 + m0;
                LOADSPLIT(base + t,           Ab[mt][0], As[mt][0]);
                LOADSPLIT(base + 320 + t,     Ab[mt][1], As[mt][1]);   // +8*40
                LOADSPLIT(base + t + 4,       Ab[mt][2], As[mt][2]);
                LOADSPLIT(base + 320 + t + 4, Ab[mt][3], As[mt][3]);
            }
            #pragma unroll
            for (int nt = 0; nt < 4; ++nt) {
                unsigned Bb0, Bb1, Bs0, Bs1;
                const int boff = (m0 + t) * P1_STRIDE + k * 32 + nt * 8 + g;
                LOADSPLIT(boff,                  Bb0, Bs0);
                LOADSPLIT(boff + 4 * P1_STRIDE,  Bb1, Bs1);
                #pragma unroll
                for (int mt = 0; mt < 2; ++mt) {
                    MMA(c2[mt][nt], Ab[mt][0], Ab[mt][1], Ab[mt][2], Ab[mt][3], Bb0, Bb1);
                    MMA(c2[mt][nt], Ab[mt][0], Ab[mt][1], Ab[mt][2], Ab[mt][3], Bs0, Bs1);
                    MMA(c2[mt][nt], As[mt][0], As[mt][1], As[mt][2], As[mt][3], Bb0, Bb1);
                }
            }
        }

        // ---- KL join: c1/c2 fragments are coordinate-identical ----
        #pragma unroll
        for (int mt = 0; mt < 2; ++mt)
            #pragma unroll
            for (int nt = 0; nt < 4; ++nt)
                #pragma unroll
                for (int e = 0; e < 4; ++e) {
                    float two = c2[mt][nt][e];
                    float one = c1[mt][nt][e];
                    kl = fmaf(two, cep_logf(__fdividef(two, one)), kl);
                }
    }

    // ---- deterministic block reduction ----
    #pragma unroll
    for (int o = 16; o > 0; o >>= 1)
        kl += __shfl_xor_sync(0xffffffffu, kl, o);

    __shared__ float sred[16];
    __shared__ bool  s_last;
    if ((tid & 31) == 0) sred[w] = kl;
    __syncthreads();

    if (tid == 0) {
        float s = 0.0f;
        #pragma unroll
        for (int x = 0; x < 16; ++x) s += sred[x];
        g_partial[b * 32 + i] = s;
        __threadfence();
        s_last = (atomicAdd(&g_count, 1) == 1023);
    }
    __syncthreads();

    // ---- last CTA: deterministic double-precision final reduce ----
    if (s_last && tid < 32) {
        __threadfence();
        double s = 0.0;
        #pragma unroll
        for (int it = 0; it < 32; ++it)
            s += (double)g_partial[it * 32 + tid];
        #pragma unroll
        for (int o = 16; o > 0; o >>= 1)
            s += __shfl_xor_sync(0xffffffffu, s, o);
        if (tid == 0) {
            out[0] = (float)(s * (1.0 / 32.0));   // / B
            g_count = 0;                          // reset for next graph replay
        }
    }
}

extern "C" void kernel_launch(void* const* d_in, const int* in_sizes, int n_in,
                              void* d_out, int out_size) {
    const float* A = (const float*)d_in[0];
    float* out = (float*)d_out;

    cudaFuncSetAttribute(assoc_kernel,
                         cudaFuncAttributeMaxDynamicSharedMemorySize, SMEM_BYTES);

    dim3 grid(32, 32);   // (i, b)
    assoc_kernel<<<grid, 512, SMEM_BYTES>>>(A, out);
}

// round 16
// speedup vs baseline: 4.6131x; 1.3003x over previous
#include <cuda_runtime.h>

// AssociatorLoss: B=32, N=32
//   one[b,i,j,k,l] = sum_m a[b,i,m,l] * a[b,j,k,m]
//   two[b,i,j,k,l] = sum_m a[b,m,k,l] * a[b,i,j,m]
//   KL = sum two * log(two/one) / B
//
// R14, third submission (two consecutive broker failures; error occurs at
// container acquisition, before compile — not kernel-induced).
// From R13's 160us tensor-core win; alu was 30.4% = cvt.tf32 tax:
//  - Si slab pre-split into (big, small) tf32 components in SMEM: GEMM-one
//    B operand and GEMM-two A operand load pre-converted bits, ZERO alu.
//  - 2-term tf32 compensation (Ab*Bb + Ab*Bs with exact-split B): mma
//    384 -> 256 per thread, error ~2^-12/product -> KL rel err ~1e-5,
//    well inside the 1e-3 gate.
//  - P1 (cube) conversions remain only for GEMM-one A (1 cvt) and
//    GEMM-two B (2 cvt + 1 sub): 192 cvt/thread (was 512).

__device__ float g_partial[1024];
__device__ int   g_count = 0;

__device__ __forceinline__ unsigned f2tf(float x) {
    unsigned r;
    asm("cvt.rna.tf32.f32 %0, %1;" : "=r"(r) : "f"(x));
    return r;
}

// split loader for P1 (big + residual), used only for GEMM-two B
#define LOADSPLIT(OFF, Bg, Sm) do {                       \
    float _x = scf[OFF];                                  \
    Bg = f2tf(_x);                                        \
    Sm = f2tf(_x - __uint_as_float(Bg));                  \
} while (0)

#define MMA(C, A0, A1, A2, A3, B0, B1)                                  \
    asm("mma.sync.aligned.m16n8k8.row.col.f32.tf32.tf32.f32 "           \
        "{%0,%1,%2,%3}, {%4,%5,%6,%7}, {%8,%9}, {%0,%1,%2,%3};"         \
        : "+f"(C[0]), "+f"(C[1]), "+f"(C[2]), "+f"(C[3])                \
        : "r"(A0), "r"(A1), "r"(A2), "r"(A3), "r"(B0), "r"(B1))

// Division-free natural log (Cephes style), ~1 ulp, no MUFU.
__device__ __forceinline__ float cep_logf(float x) {
    int ix = __float_as_int(x);
    int t  = ix - 0x3f3504f3;
    int e  = t >> 23;
    float z = __int_as_float(ix - (t & 0xff800000));   // [0.7071, 1.4142)
    float f = z - 1.0f;
    float p =              7.0376836292e-2f;
    p = fmaf(p, f, -1.1514610310e-1f);
    p = fmaf(p, f,  1.1676998740e-1f);
    p = fmaf(p, f, -1.2420140846e-1f);
    p = fmaf(p, f,  1.4249322787e-1f);
    p = fmaf(p, f, -1.6668057665e-1f);
    p = fmaf(p, f,  2.0000714765e-1f);
    p = fmaf(p, f, -2.4999993993e-1f);
    p = fmaf(p, f,  3.3333331174e-1f);
    float f2 = f * f;
    float y = fmaf(f * f2, p, -0.5f * f2);
    return fmaf((float)e, 0.69314718056f, f + y);
}

// SMEM (float indices):
//   P1:       cube, P1[x][y*32+z] at x*1032 + y*32+z          (132,096 B)
//   Si_big:   tf32(a[i,y,z])        at SIB_F + y*40 + z         (5,120 B)
//   Si_small: tf32(a - big)         at SIS_F + y*40 + z         (5,120 B)
#define P1_STRIDE 1032
#define SIB_F   33024
#define SIS_F   34304
#define SIB_F4  8256
#define SIS_F4  8576
#define SMEM_BYTES 142336

__global__ __launch_bounds__(512, 1)
void assoc_kernel(const float* __restrict__ A, float* __restrict__ out) {
    extern __shared__ float scf[];
    float4* sc4 = reinterpret_cast<float4*>(scf);

    const int i = blockIdx.x;                   // 0..31
    const int b = blockIdx.y;                   // 0..31
    const int tid = threadIdx.x;
    const float4* ab4 = reinterpret_cast<const float4*>(A + b * 32768);

    // ---- stage padded cube P1 ----
    #pragma unroll
    for (int it = 0; it < 16; ++it) {
        int gdx = it * 512 + tid;               // x*256 + c4
        sc4[(gdx >> 8) * 258 + (gdx & 255)] = ab4[gdx];
    }
    // ---- stage pre-split slab Si (big + small), stride-40 padded ----
    if (tid < 256) {
        float4 v = ab4[i * 256 + tid];
        unsigned bx = f2tf(v.x), by = f2tf(v.y), bz = f2tf(v.z), bw = f2tf(v.w);
        float4 big = make_float4(__uint_as_float(bx), __uint_as_float(by),
                                 __uint_as_float(bz), __uint_as_float(bw));
        float4 sml = make_float4(
            __uint_as_float(f2tf(v.x - big.x)), __uint_as_float(f2tf(v.y - big.y)),
            __uint_as_float(f2tf(v.z - big.z)), __uint_as_float(f2tf(v.w - big.w)));
        int pos = (tid >> 3) * 10 + (tid & 7);
        sc4[SIB_F4 + pos] = big;
        sc4[SIS_F4 + pos] = sml;
    }
    __syncthreads();

    const int lane = tid & 31;
    const int w    = tid >> 5;       // warp 0..15
    const int g    = lane >> 2;      // groupID 0..7
    const int t    = lane & 3;       // threadID-in-group 0..3

    float kl = 0.0f;

    #pragma unroll 1
    for (int pk = 0; pk < 2; ++pk) {
        const int k = w + pk * 16;              // this warp's k

        float c1[2][4][4], c2[2][4][4];         // [mtile][ntile][4]
        #pragma unroll
        for (int mt = 0; mt < 2; ++mt)
            #pragma unroll
            for (int nt = 0; nt < 4; ++nt)
                #pragma unroll
                for (int e = 0; e < 4; ++e) { c1[mt][nt][e] = 0.f; c2[mt][nt][e] = 0.f; }

        #pragma unroll
        for (int kt = 0; kt < 4; ++kt) {        // K=32 in 4 k-tiles of 8
            const int m0 = kt * 8;
            unsigned Ab[2][4];

            // ===== GEMM "one": A' = tf32(a[j,k,m]) (P1), B = Si split =====
            #pragma unroll
            for (int mt = 0; mt < 2; ++mt) {
                const int base = (mt * 16 + g) * P1_STRIDE + k * 32 + m0;
                Ab[mt][0] = f2tf(scf[base + t]);
                Ab[mt][1] = f2tf(scf[base + 8 * P1_STRIDE + t]);
                Ab[mt][2] = f2tf(scf[base + t + 4]);
                Ab[mt][3] = f2tf(scf[base + 8 * P1_STRIDE + t + 4]);
            }
            #pragma unroll
            for (int nt = 0; nt < 4; ++nt) {
                const int bo = (m0 + t) * 40 + nt * 8 + g;
                unsigned Bb0 = __float_as_uint(scf[SIB_F + bo]);
                unsigned Bb1 = __float_as_uint(scf[SIB_F + bo + 160]); // +4*40
                unsigned Bs0 = __float_as_uint(scf[SIS_F + bo]);
                unsigned Bs1 = __float_as_uint(scf[SIS_F + bo + 160]);
                #pragma unroll
                for (int mt = 0; mt < 2; ++mt) {
                    MMA(c1[mt][nt], Ab[mt][0], Ab[mt][1], Ab[mt][2], Ab[mt][3], Bb0, Bb1);
                    MMA(c1[mt][nt], Ab[mt][0], Ab[mt][1], Ab[mt][2], Ab[mt][3], Bs0, Bs1);
                }
            }

            // ===== GEMM "two": A = Si_big (pre-split), B = split(a[m,k,l]) =====
            #pragma unroll
            for (int mt = 0; mt < 2; ++mt) {
                const int base = SIB_F + (mt * 16 + g) * 40 + m0;
                Ab[mt][0] = __float_as_uint(scf[base + t]);
                Ab[mt][1] = __float_as_uint(scf[base + 320 + t]);      // +8*40
                Ab[mt][2] = __float_as_uint(scf[base + t + 4]);
                Ab[mt][3] = __float_as_uint(scf[base + 320 + t + 4]);
            }
            #pragma unroll
            for (int nt = 0; nt < 4; ++nt) {
                unsigned Bb0, Bb1, Bs0, Bs1;
                const int bo = (m0 + t) * P1_STRIDE + k * 32 + nt * 8 + g;
                LOADSPLIT(bo,                 Bb0, Bs0);
                LOADSPLIT(bo + 4 * P1_STRIDE, Bb1, Bs1);
                #pragma unroll
                for (int mt = 0; mt < 2; ++mt) {
                    MMA(c2[mt][nt], Ab[mt][0], Ab[mt][1], Ab[mt][2], Ab[mt][3], Bb0, Bb1);
                    MMA(c2[mt][nt], Ab[mt][0], Ab[mt][1], Ab[mt][2], Ab[mt][3], Bs0, Bs1);
                }
            }
        }

        // ---- KL join: c1/c2 fragments are coordinate-identical ----
        #pragma unroll
        for (int mt = 0; mt < 2; ++mt)
            #pragma unroll
            for (int nt = 0; nt < 4; ++nt)
                #pragma unroll
                for (int e = 0; e < 4; ++e) {
                    float two = c2[mt][nt][e];
                    float one = c1[mt][nt][e];
                    kl = fmaf(two, cep_logf(__fdividef(two, one)), kl);
                }
    }

    // ---- deterministic block reduction ----
    #pragma unroll
    for (int o = 16; o > 0; o >>= 1)
        kl += __shfl_xor_sync(0xffffffffu, kl, o);

    __shared__ float sred[16];
    __shared__ bool  s_last;
    if ((tid & 31) == 0) sred[w] = kl;
    __syncthreads();

    if (tid == 0) {
        float s = 0.0f;
        #pragma unroll
        for (int x = 0; x < 16; ++x) s += sred[x];
        g_partial[b * 32 + i] = s;
        __threadfence();
        s_last = (atomicAdd(&g_count, 1) == 1023);
    }
    __syncthreads();

    // ---- last CTA: deterministic double-precision final reduce ----
    if (s_last && tid < 32) {
        __threadfence();
        double s = 0.0;
        #pragma unroll
        for (int it = 0; it < 32; ++it)
            s += (double)g_partial[it * 32 + tid];
        #pragma unroll
        for (int o = 16; o > 0; o >>= 1)
            s += __shfl_xor_sync(0xffffffffu, s, o);
        if (tid == 0) {
            out[0] = (float)(s * (1.0 / 32.0));   // / B
            g_count = 0;                          // reset for next graph replay
        }
    }
}

extern "C" void kernel_launch(void* const* d_in, const int* in_sizes, int n_in,
                              void* d_out, int out_size) {
    const float* A = (const float*)d_in[0];
    float* out = (float*)d_out;

    cudaFuncSetAttribute(assoc_kernel,
                         cudaFuncAttributeMaxDynamicSharedMemorySize, SMEM_BYTES);

    dim3 grid(32, 32);   // (i, b)
    assoc_kernel<<<grid, 512, SMEM_BYTES>>>(A, out);
}